// round 13
// baseline (speedup 1.0000x reference)
#include <cuda_runtime.h>
#include <math.h>
#include <stdint.h>

#define N_LEVELS 16
#define N_POINTS 524288
#define HASH_MASK 0x7FFFFu       // hashed level size = 2^19 exactly
#define P1 2654435761u
#define P2 805459861u

#define NBUCK 32768              // 32^3 Morton buckets (~16 pts/bucket)

// Static scratch (no allocation allowed)
__device__ uint4    g_hist4[NBUCK / 4];   // counts -> global exclusive offsets
__device__ unsigned g_rank[N_POINTS];     // within-bucket rank (from histo)
__device__ float4   g_sorted[N_POINTS];   // (x,y,z, bitcast(orig index))

struct Scales { float s[N_LEVELS]; };

// ---------------- sort pipeline ----------------

__device__ __forceinline__ unsigned spread3(unsigned v) {
    v &= 0x3Fu;
    v = (v | (v << 16)) & 0x030000FFu;
    v = (v | (v << 8))  & 0x0300F00Fu;
    v = (v | (v << 4))  & 0x030C30C3u;
    v = (v | (v << 2))  & 0x09249249u;
    return v;
}

__device__ __forceinline__ unsigned bucket_of(float x, float y, float z) {
    unsigned cx = min((unsigned)(x * 32.0f), 31u);
    unsigned cy = min((unsigned)(y * 32.0f), 31u);
    unsigned cz = min((unsigned)(z * 32.0f), 31u);
    return spread3(cx) | (spread3(cy) << 1) | (spread3(cz) << 2);  // 15-bit Morton
}

// histo: count AND capture each point's within-bucket rank (the atomic's
// return value) so the scatter is atomic-free. Bucket id is NOT stored —
// the scatter recomputes it (ALU is free; traffic is not).
__global__ void k_histo(const float* __restrict__ inputs) {
    unsigned i = blockIdx.x * blockDim.x + threadIdx.x;
    float x = inputs[i * 3 + 0];
    float y = inputs[i * 3 + 1];
    float z = inputs[i * 3 + 2];
    unsigned b = bucket_of(x, y, z);
    unsigned* hist = reinterpret_cast<unsigned*>(g_hist4);
    g_rank[i] = atomicAdd(&hist[b], 1u);   // coalesced store
}

// Single-kernel scan: ONE 1024-thread block owns all 32768 counters.
// Thread t serially prefixes its 32 contiguous elems (8 x uint4), block-scans
// the 1024 chunk totals in SMEM, writes back GLOBAL exclusive offsets.
// ~128KB read + 128KB write on one SM ≈ 2-3us; replaces scanA+scanB+btot.
__global__ __launch_bounds__(1024) void k_scan() {
    __shared__ unsigned s[1024];
    unsigned t = threadIdx.x;

    uint4 v[8];
    unsigned sum = 0u;
#pragma unroll
    for (int k = 0; k < 8; k++) {
        v[k] = g_hist4[t * 8u + k];
        sum += v[k].x + v[k].y + v[k].z + v[k].w;
    }

    s[t] = sum;
    __syncthreads();
    for (int d = 1; d < 1024; d <<= 1) {
        unsigned add = (t >= (unsigned)d) ? s[t - d] : 0u;
        __syncthreads();
        s[t] += add;
        __syncthreads();
    }
    unsigned run = s[t] - sum;     // global exclusive prefix of this chunk

#pragma unroll
    for (int k = 0; k < 8; k++) {
        uint4 o;
        o.x = run;             run += v[k].x;
        o.y = run;             run += v[k].y;
        o.z = run;             run += v[k].z;
        o.w = run;             run += v[k].w;
        g_hist4[t * 8u + k] = o;
    }
}

// Scatter: ATOMIC-FREE. slot = captured rank + global bucket offset.
__global__ void k_scatter(const float* __restrict__ inputs) {
    unsigned i = blockIdx.x * blockDim.x + threadIdx.x;
    float x = inputs[i * 3 + 0];
    float y = inputs[i * 3 + 1];
    float z = inputs[i * 3 + 2];
    unsigned b = bucket_of(x, y, z);       // recomputed, no stored bucket
    const unsigned* hist = reinterpret_cast<const unsigned*>(g_hist4);
    unsigned pos = g_rank[i] + __ldg(&hist[b]);
    g_sorted[pos] = make_float4(x, y, z, __uint_as_float(i));
}

// ---------------- main encode ----------------
// (Exact R7 version: 147us measured, L1-wavefront-bound at its floor.
// One thread per sorted point; a warp = 32 spatially-clustered points ->
// lane addresses collapse to few sectors on coarse/mid levels.)

__global__ __launch_bounds__(256) void hashenc_main(
    const float2* __restrict__ emb,
    const int*    __restrict__ offs,
    float2*       __restrict__ out,
    Scales sc)
{
    const unsigned kRes[5] = {16u, 23u, 31u, 43u, 59u};

    unsigned i = blockIdx.x * 256u + threadIdx.x;
    float4 pt = g_sorted[i];                       // 1 coalesced LDG.128
    float x = pt.x, y = pt.y, z = pt.z;
    unsigned p = __float_as_uint(pt.w);
    float* orow = (float*)out + (size_t)p * 32u;   // 128B row, 16B aligned

#pragma unroll
    for (int h = 0; h < 2; h++) {                  // two halves of 8 levels
        float acc[16];
#pragma unroll
        for (int l8 = 0; l8 < 8; l8++) {
            const int l = h * 8 + l8;
            float scale = sc.s[l];
            // plain fp32 multiply (bit-exact vs jnp inputs*scale)
            float px = x * scale, py = y * scale, pz = z * scale;
            float fx0 = floorf(px), fy0 = floorf(py), fz0 = floorf(pz);
            float fx = px - fx0, fy = py - fy0, fz = pz - fz0;
            unsigned gx = (unsigned)fx0, gy = (unsigned)fy0, gz = (unsigned)fz0;
            unsigned base = (unsigned)__ldg(&offs[l]);

            unsigned idx[8];
            if (l >= 5) {
                // hashed: (cx*1 ^ cy*P1 ^ cz*P2) & (2^19-1)
                unsigned hy0 = gy * P1, hy1 = hy0 + P1;
                unsigned hz0 = gz * P2, hz1 = hz0 + P2;
                unsigned s00 = hy0 ^ hz0, s10 = hy1 ^ hz0;
                unsigned s01 = hy0 ^ hz1, s11 = hy1 ^ hz1;
                unsigned x0 = gx, x1 = gx + 1u;
                idx[0] = (x0 ^ s00) & HASH_MASK;
                idx[1] = (x1 ^ s00) & HASH_MASK;
                idx[2] = (x0 ^ s10) & HASH_MASK;
                idx[3] = (x1 ^ s10) & HASH_MASK;
                idx[4] = (x0 ^ s01) & HASH_MASK;
                idx[5] = (x1 ^ s01) & HASH_MASK;
                idx[6] = (x0 ^ s11) & HASH_MASK;
                idx[7] = (x1 ^ s11) & HASH_MASK;
            } else {
                // dense: row-major within res^3, corners clamped to res-1
                unsigned res = kRes[l];
                unsigned rm1 = res - 1u;
                unsigned rr  = res * res;
                unsigned x0 = min(gx, rm1),       x1 = min(gx + 1u, rm1);
                unsigned y0 = min(gy, rm1) * res, y1 = min(gy + 1u, rm1) * res;
                unsigned z0 = min(gz, rm1) * rr,  z1 = min(gz + 1u, rm1) * rr;
                idx[0] = x0 + y0 + z0;
                idx[1] = x1 + y0 + z0;
                idx[2] = x0 + y1 + z0;
                idx[3] = x1 + y1 + z0;
                idx[4] = x0 + y0 + z1;
                idx[5] = x1 + y0 + z1;
                idx[6] = x0 + y1 + z1;
                idx[7] = x1 + y1 + z1;
            }

            float2 e[8];
#pragma unroll
            for (int c = 0; c < 8; c++)
                e[c] = __ldg(&emb[base + idx[c]]);

            float wx[2] = {1.0f - fx, fx};
            float wy[2] = {1.0f - fy, fy};
            float wz[2] = {1.0f - fz, fz};
            float ox = 0.0f, oy = 0.0f;
#pragma unroll
            for (int c = 0; c < 8; c++) {
                float w = wx[c & 1] * wy[(c >> 1) & 1] * wz[(c >> 2) & 1];
                ox += w * e[c].x;
                oy += w * e[c].y;
            }
            acc[l8 * 2 + 0] = ox;
            acc[l8 * 2 + 1] = oy;
        }
        // Half-row store: 4x STG.128 to this point's contiguous 128B row.
#pragma unroll
        for (int q = 0; q < 4; q++) {
            float4 v = make_float4(acc[q * 4 + 0], acc[q * 4 + 1],
                                   acc[q * 4 + 2], acc[q * 4 + 3]);
            __stcs((float4*)(orow + h * 16) + q, v);
        }
    }
}

// ---------------- launch ----------------

extern "C" void kernel_launch(void* const* d_in, const int* in_sizes, int n_in,
                              void* d_out, int out_size)
{
    const float*  inputs = (const float*)d_in[0];
    const float2* emb    = (const float2*)d_in[1];
    const int*    offs   = (const int*)d_in[2];
    float2*       out    = (float2*)d_out;

    // scale[l] = float32(16 * (2^(7/15))^l), computed in double so the float32
    // cast absorbs any sub-ulp libm difference vs numpy.
    Scales sc;
    double ratio = exp2(7.0 / 15.0);
    for (int l = 0; l < N_LEVELS; l++)
        sc.s[l] = (float)(16.0 * pow(ratio, (double)l));

    // Zero histogram via a memset node (no kernel, graph-capturable, no alloc)
    void* hist_ptr = nullptr;
    cudaGetSymbolAddress(&hist_ptr, g_hist4);
    cudaMemsetAsync(hist_ptr, 0, NBUCK * sizeof(unsigned));

    k_histo  <<<N_POINTS / 256, 256>>>(inputs);
    k_scan   <<<1, 1024>>>();
    k_scatter<<<N_POINTS / 256, 256>>>(inputs);
    hashenc_main<<<N_POINTS / 256, 256>>>(emb, offs, out, sc);
}

// round 14
// speedup vs baseline: 1.0615x; 1.0615x over previous
#include <cuda_runtime.h>
#include <math.h>
#include <stdint.h>

#define N_LEVELS 16
#define N_POINTS 524288
#define HASH_MASK 0x7FFFFu       // hashed level size = 2^19 exactly
#define P1 2654435761u
#define P2 805459861u

#define NBUCK 32768              // 32^3 Morton buckets (~16 pts/bucket)
#define SCAN_BLOCKS 32           // 32 blocks x 1024 elems

// Static scratch (no allocation allowed). __device__ globals are
// zero-initialized at load; the pipeline leaves g_hist4 zeroed after every
// launch (scanA zeroes it), so no memset node is needed.
__device__ uint4    g_hist4[NBUCK / 4];   // counts; RETURNED TO ZERO by scanA
__device__ uint4    g_off4[NBUCK / 4];    // exclusive offsets within scan-block
__device__ unsigned g_btot[SCAN_BLOCKS];  // scan-block totals -> exclusive
__device__ unsigned g_rank[N_POINTS];     // within-bucket rank (from histo)
__device__ float4   g_sorted[N_POINTS];   // (x,y,z, bitcast(orig index))

struct Scales { float s[N_LEVELS]; };

// ---------------- sort pipeline ----------------

__device__ __forceinline__ unsigned spread3(unsigned v) {
    v &= 0x3Fu;
    v = (v | (v << 16)) & 0x030000FFu;
    v = (v | (v << 8))  & 0x0300F00Fu;
    v = (v | (v << 4))  & 0x030C30C3u;
    v = (v | (v << 2))  & 0x09249249u;
    return v;
}

__device__ __forceinline__ unsigned bucket_of(float x, float y, float z) {
    unsigned cx = min((unsigned)(x * 32.0f), 31u);
    unsigned cy = min((unsigned)(y * 32.0f), 31u);
    unsigned cz = min((unsigned)(z * 32.0f), 31u);
    return spread3(cx) | (spread3(cy) << 1) | (spread3(cz) << 2);  // 15-bit Morton
}

// histo: count AND capture each point's within-bucket rank (the atomic's
// return value) so the scatter is atomic-free.
__global__ void k_histo(const float* __restrict__ inputs) {
    unsigned i = blockIdx.x * blockDim.x + threadIdx.x;
    float x = inputs[i * 3 + 0];
    float y = inputs[i * 3 + 1];
    float z = inputs[i * 3 + 2];
    unsigned b = bucket_of(x, y, z);
    unsigned* hist = reinterpret_cast<unsigned*>(g_hist4);
    g_rank[i] = atomicAdd(&hist[b], 1u);   // coalesced store
}

// scanA: 32 blocks x 256 threads; thread t owns ONE uint4 (warp = 512B
// contiguous -> fully coalesced; the R13 single-block layout was 32x
// uncoalesced and cost ~10us). Also ZEROES g_hist4 for the next replay,
// replacing the memset node.
__global__ __launch_bounds__(256) void k_scanA() {
    __shared__ unsigned s[256];
    unsigned t = threadIdx.x;
    unsigned gi = blockIdx.x * 256u + t;

    uint4 v = g_hist4[gi];
    unsigned sum = v.x + v.y + v.z + v.w;

    s[t] = sum;
    __syncthreads();
    for (int d = 1; d < 256; d <<= 1) {
        unsigned add = (t >= (unsigned)d) ? s[t - d] : 0u;
        __syncthreads();
        s[t] += add;
        __syncthreads();
    }
    unsigned run = s[t] - sum;     // exclusive prefix of this chunk in block

    uint4 o;
    o.x = run;
    o.y = run + v.x;
    o.z = run + v.x + v.y;
    o.w = run + v.x + v.y + v.z;
    g_off4[gi]  = o;
    g_hist4[gi] = make_uint4(0u, 0u, 0u, 0u);   // ready for next launch

    if (t == 255u) g_btot[blockIdx.x] = s[255];
}

// scanB: one warp exclusive-scans the 32 block totals via shuffles.
__global__ void k_scanB() {
    unsigned t = threadIdx.x;           // 32 threads
    unsigned v = g_btot[t];
    unsigned x = v;
#pragma unroll
    for (int d = 1; d < 32; d <<= 1) {
        unsigned n = __shfl_up_sync(0xFFFFFFFFu, x, d);
        if (t >= (unsigned)d) x += n;
    }
    g_btot[t] = x - v;                  // exclusive
}

// Scatter: ATOMIC-FREE. slot = captured rank + bucket offset + block offset.
// Bucket recomputed from coords (ALU is free; traffic is not).
__global__ void k_scatter(const float* __restrict__ inputs) {
    unsigned i = blockIdx.x * blockDim.x + threadIdx.x;
    float x = inputs[i * 3 + 0];
    float y = inputs[i * 3 + 1];
    float z = inputs[i * 3 + 2];
    unsigned b = bucket_of(x, y, z);
    const unsigned* off = reinterpret_cast<const unsigned*>(g_off4);
    unsigned pos = g_rank[i] + __ldg(&off[b]) + __ldg(&g_btot[b >> 10]);
    g_sorted[pos] = make_float4(x, y, z, __uint_as_float(i));
}

// ---------------- main encode ----------------
// (Exact R7 version: ~148us measured, L1-wavefront-bound at its floor.
// One thread per sorted point; a warp = 32 spatially-clustered points ->
// lane addresses collapse to few sectors on coarse/mid levels.)

__global__ __launch_bounds__(256) void hashenc_main(
    const float2* __restrict__ emb,
    const int*    __restrict__ offs,
    float2*       __restrict__ out,
    Scales sc)
{
    const unsigned kRes[5] = {16u, 23u, 31u, 43u, 59u};

    unsigned i = blockIdx.x * 256u + threadIdx.x;
    float4 pt = g_sorted[i];                       // 1 coalesced LDG.128
    float x = pt.x, y = pt.y, z = pt.z;
    unsigned p = __float_as_uint(pt.w);
    float* orow = (float*)out + (size_t)p * 32u;   // 128B row, 16B aligned

#pragma unroll
    for (int h = 0; h < 2; h++) {                  // two halves of 8 levels
        float acc[16];
#pragma unroll
        for (int l8 = 0; l8 < 8; l8++) {
            const int l = h * 8 + l8;
            float scale = sc.s[l];
            // plain fp32 multiply (bit-exact vs jnp inputs*scale)
            float px = x * scale, py = y * scale, pz = z * scale;
            float fx0 = floorf(px), fy0 = floorf(py), fz0 = floorf(pz);
            float fx = px - fx0, fy = py - fy0, fz = pz - fz0;
            unsigned gx = (unsigned)fx0, gy = (unsigned)fy0, gz = (unsigned)fz0;
            unsigned base = (unsigned)__ldg(&offs[l]);

            unsigned idx[8];
            if (l >= 5) {
                // hashed: (cx*1 ^ cy*P1 ^ cz*P2) & (2^19-1)
                unsigned hy0 = gy * P1, hy1 = hy0 + P1;
                unsigned hz0 = gz * P2, hz1 = hz0 + P2;
                unsigned s00 = hy0 ^ hz0, s10 = hy1 ^ hz0;
                unsigned s01 = hy0 ^ hz1, s11 = hy1 ^ hz1;
                unsigned x0 = gx, x1 = gx + 1u;
                idx[0] = (x0 ^ s00) & HASH_MASK;
                idx[1] = (x1 ^ s00) & HASH_MASK;
                idx[2] = (x0 ^ s10) & HASH_MASK;
                idx[3] = (x1 ^ s10) & HASH_MASK;
                idx[4] = (x0 ^ s01) & HASH_MASK;
                idx[5] = (x1 ^ s01) & HASH_MASK;
                idx[6] = (x0 ^ s11) & HASH_MASK;
                idx[7] = (x1 ^ s11) & HASH_MASK;
            } else {
                // dense: row-major within res^3, corners clamped to res-1
                unsigned res = kRes[l];
                unsigned rm1 = res - 1u;
                unsigned rr  = res * res;
                unsigned x0 = min(gx, rm1),       x1 = min(gx + 1u, rm1);
                unsigned y0 = min(gy, rm1) * res, y1 = min(gy + 1u, rm1) * res;
                unsigned z0 = min(gz, rm1) * rr,  z1 = min(gz + 1u, rm1) * rr;
                idx[0] = x0 + y0 + z0;
                idx[1] = x1 + y0 + z0;
                idx[2] = x0 + y1 + z0;
                idx[3] = x1 + y1 + z0;
                idx[4] = x0 + y0 + z1;
                idx[5] = x1 + y0 + z1;
                idx[6] = x0 + y1 + z1;
                idx[7] = x1 + y1 + z1;
            }

            float2 e[8];
#pragma unroll
            for (int c = 0; c < 8; c++)
                e[c] = __ldg(&emb[base + idx[c]]);

            float wx[2] = {1.0f - fx, fx};
            float wy[2] = {1.0f - fy, fy};
            float wz[2] = {1.0f - fz, fz};
            float ox = 0.0f, oy = 0.0f;
#pragma unroll
            for (int c = 0; c < 8; c++) {
                float w = wx[c & 1] * wy[(c >> 1) & 1] * wz[(c >> 2) & 1];
                ox += w * e[c].x;
                oy += w * e[c].y;
            }
            acc[l8 * 2 + 0] = ox;
            acc[l8 * 2 + 1] = oy;
        }
        // Half-row store: 4x STG.128 to this point's contiguous 128B row.
#pragma unroll
        for (int q = 0; q < 4; q++) {
            float4 v = make_float4(acc[q * 4 + 0], acc[q * 4 + 1],
                                   acc[q * 4 + 2], acc[q * 4 + 3]);
            __stcs((float4*)(orow + h * 16) + q, v);
        }
    }
}

// ---------------- launch ----------------

extern "C" void kernel_launch(void* const* d_in, const int* in_sizes, int n_in,
                              void* d_out, int out_size)
{
    const float*  inputs = (const float*)d_in[0];
    const float2* emb    = (const float2*)d_in[1];
    const int*    offs   = (const int*)d_in[2];
    float2*       out    = (float2*)d_out;

    // scale[l] = float32(16 * (2^(7/15))^l), computed in double so the float32
    // cast absorbs any sub-ulp libm difference vs numpy.
    Scales sc;
    double ratio = exp2(7.0 / 15.0);
    for (int l = 0; l < N_LEVELS; l++)
        sc.s[l] = (float)(16.0 * pow(ratio, (double)l));

    // No memset: g_hist4 starts zeroed (module load) and scanA re-zeroes it
    // every launch -> graph-replay deterministic.
    k_histo  <<<N_POINTS / 256, 256>>>(inputs);
    k_scanA  <<<SCAN_BLOCKS, 256>>>();
    k_scanB  <<<1, 32>>>();
    k_scatter<<<N_POINTS / 256, 256>>>(inputs);
    hashenc_main<<<N_POINTS / 256, 256>>>(emb, offs, out, sc);
}